// round 9
// baseline (speedup 1.0000x reference)
#include <cuda_runtime.h>
#include <cfloat>

// Problem constants (from reference)
#define PB 7      // pooled bins per dim
#define HH 50
#define WW 50
#define CC 512
#define BB 2
#define RR 64
#define C4 (CC / 4)   // 128 float4 per pixel

// One CTA (256 threads) per (b, r, py, px) output bin.
//   c4   = tid & 127 : float4 channel slice
//   half = tid >> 7  : which half of the bin's pixels this thread gathers
// The n = sy*sx (<=16) pixels are split statically: half 0 takes the first
// ceil(n/2), half 1 the rest. Each thread batch-loads <= 8 independent
// LDG.128 (32 data regs), halves merge via one 2KB smem exchange. This
// halves the per-warp dependent chain and doubles per-bin parallelism
// without blowing the register file (the R7 failure mode).
//
// Facts proved from input ranges: extent in [7,26) => bin sizes sy,sx in
// [1,4]; window always fully in-bounds (max index y0+h-1 <= 48 < 50).

__device__ __forceinline__ void vmax(float4& m, float4 v) {
    m.x = fmaxf(m.x, v.x);
    m.y = fmaxf(m.y, v.y);
    m.z = fmaxf(m.z, v.z);
    m.w = fmaxf(m.w, v.w);
}

template<int SY, int SX, int HALF>
__device__ __forceinline__ float4 binmax_half(const float4* __restrict__ p) {
    constexpr int N   = SY * SX;
    constexpr int N0  = (N + 1) / 2;            // pixels for half 0
    constexpr int K0  = (HALF == 0) ? 0 : N0;   // first pixel index
    constexpr int CNT = (HALF == 0) ? N0 : N - N0;

    float4 m = make_float4(-FLT_MAX, -FLT_MAX, -FLT_MAX, -FLT_MAX);
    if (CNT > 0) {
        float4 v[CNT > 0 ? CNT : 1];
        #pragma unroll
        for (int j = 0; j < CNT; ++j) {
            int k  = K0 + j;              // compile-time after unroll
            int dy = k / SX, dx = k % SX;
            v[j] = __ldg(p + (dy * WW + dx) * C4);
        }
        m = v[0];
        #pragma unroll
        for (int j = 1; j < CNT; ++j)
            vmax(m, v[j]);
    }
    return m;
}

template<int SY, int SX>
__device__ __forceinline__ float4 binmax2(const float4* __restrict__ p, int half) {
    // half is uniform per warp (tid>>7): no divergence.
    return (half == 0) ? binmax_half<SY, SX, 0>(p)
                       : binmax_half<SY, SX, 1>(p);
}

__global__ __launch_bounds__(2 * C4) void roipool_kernel(
    const float4* __restrict__ fm,    // (B,H,W,C) as float4
    const int*    __restrict__ rois,  // (B,R,4) int32: y0,x0,h,w
    float4*       __restrict__ out)   // (B,R,P,P,C) as float4
{
    __shared__ float4 part[C4];       // half-1 partial maxima

    int idx = blockIdx.x;                 // b*R*P*P + r*P*P + py*P + px
    int px = idx % PB;
    int t  = idx / PB;
    int py = t % PB;
    t /= PB;
    int r = t % RR;
    int b = t / RR;

    int c4   = threadIdx.x & (C4 - 1);
    int half = threadIdx.x >> 7;

    const int4 roi = __ldg((const int4*)(rois + (b * RR + r) * 4));
    int y0 = roi.x, x0 = roi.y, h = roi.z, w = roi.w;

    // Bin bounds — fp32 arithmetic exactly as the reference:
    // step = extent/7 (fp32), start = trunc(i*step), end = trunc((i+1)*step),
    // last bin end = extent, size = max(end-start, 1).
    float stepy = (float)h / 7.0f;
    float stepx = (float)w / 7.0f;
    int ys = (int)((float)py * stepy);
    int ye = (py == PB - 1) ? h : (int)((float)(py + 1) * stepy);
    int sy = max(ye - ys, 1);
    int xs = (int)((float)px * stepx);
    int xe = (px == PB - 1) ? w : (int)((float)(px + 1) * stepx);
    int sx = max(xe - xs, 1);

    const float4* p = fm
        + ((size_t)((b * HH + (y0 + ys)) * WW + (x0 + xs))) * C4
        + c4;

    float4 m;
    int code = (sy - 1) * 4 + (sx - 1);   // uniform across CTA: no divergence
    switch (code) {
        case  0: m = binmax2<1,1>(p, half); break;
        case  1: m = binmax2<1,2>(p, half); break;
        case  2: m = binmax2<1,3>(p, half); break;
        case  3: m = binmax2<1,4>(p, half); break;
        case  4: m = binmax2<2,1>(p, half); break;
        case  5: m = binmax2<2,2>(p, half); break;
        case  6: m = binmax2<2,3>(p, half); break;
        case  7: m = binmax2<2,4>(p, half); break;
        case  8: m = binmax2<3,1>(p, half); break;
        case  9: m = binmax2<3,2>(p, half); break;
        case 10: m = binmax2<3,3>(p, half); break;
        case 11: m = binmax2<3,4>(p, half); break;
        case 12: m = binmax2<4,1>(p, half); break;
        case 13: m = binmax2<4,2>(p, half); break;
        case 14: m = binmax2<4,3>(p, half); break;
        default: m = binmax2<4,4>(p, half); break;
    }

    if (half == 1)
        part[c4] = m;
    __syncthreads();

    if (half == 0) {
        vmax(m, part[c4]);
        out[(size_t)idx * C4 + c4] = m;
    }
}

extern "C" void kernel_launch(void* const* d_in, const int* in_sizes, int n_in,
                              void* d_out, int out_size) {
    const float4* fm   = (const float4*)d_in[0];  // x_maps float32 (2,50,50,512)
    const int*    rois = (const int*)d_in[1];     // x_rois int32 (2,64,4)
    float4*       out  = (float4*)d_out;          // (2,64,7,7,512) float32

    int nblocks = BB * RR * PB * PB;  // 6272
    roipool_kernel<<<nblocks, 2 * C4>>>(fm, rois, out);
}